// round 14
// baseline (speedup 1.0000x reference)
#include <cuda_runtime.h>
#include <cuda_bf16.h>
#include <cuda_fp16.h>
#include <cstdint>

// x: [8,32,256,64] f32 | baseK: [8,64,256,256] f32 | W: [64,224] | b: [64] | y: [8,64,256,64]
#define B_   8
#define F_   32
#define C_   256
#define M_   64
#define CO_  64
#define PAIRS 512
#define LDA  264             // padded row stride (halves): 528B

__device__ __half g_scratch_h[6 * PAIRS * F_ * C_];   // hop results, fp16
__device__ __half g_xTh[PAIRS * F_ * C_];             // fp16(x) transposed
__device__ __half g_xT_lo[PAIRS * F_ * C_];           // fp16 residual of x

// ---------------- helpers ----------------
__device__ __forceinline__ uint32_t smem_u32(const void* p) {
    uint32_t a;
    asm("{ .reg .u64 t; cvta.to.shared.u64 t, %1; cvt.u32.u64 %0, t; }" : "=r"(a) : "l"(p));
    return a;
}
__device__ __forceinline__ uint32_t pack_h2(float x, float y) {
    uint32_t r;
    asm("cvt.rn.f16x2.f32 %0, %1, %2;" : "=r"(r) : "f"(y), "f"(x));
    return r;
}
__device__ __forceinline__ void split2h(float x, float y, uint32_t& hi, uint32_t& lo) {
    hi = pack_h2(x, y);
    float hx, hy;
    asm("{ .reg .f16 a,b; mov.b32 {a,b}, %2; cvt.f32.f16 %0, a; cvt.f32.f16 %1, b; }"
        : "=f"(hx), "=f"(hy) : "r"(hi));
    lo = pack_h2(x - hx, y - hy);
}
__device__ __forceinline__ void ldm_x4(uint32_t* r, uint32_t addr) {
    asm volatile("ldmatrix.sync.aligned.m8n8.x4.shared.b16 {%0,%1,%2,%3}, [%4];"
                 : "=r"(r[0]), "=r"(r[1]), "=r"(r[2]), "=r"(r[3]) : "r"(addr));
}
__device__ __forceinline__ void ldm_x4t(uint32_t* r, uint32_t addr) {
    asm volatile("ldmatrix.sync.aligned.m8n8.x4.trans.shared.b16 {%0,%1,%2,%3}, [%4];"
                 : "=r"(r[0]), "=r"(r[1]), "=r"(r[2]), "=r"(r[3]) : "r"(addr));
}
__device__ __forceinline__ void mma_f16(float* d, const uint32_t* a, const uint32_t* b) {
    asm volatile("mma.sync.aligned.m16n8k16.row.col.f32.f16.f16.f32 "
                 "{%0,%1,%2,%3}, {%4,%5,%6,%7}, {%8,%9}, {%0,%1,%2,%3};"
                 : "+f"(d[0]), "+f"(d[1]), "+f"(d[2]), "+f"(d[3])
                 : "r"(a[0]), "r"(a[1]), "r"(a[2]), "r"(a[3]), "r"(b[0]), "r"(b[1]));
}
__device__ __forceinline__ void bar_arrive(int id, int cnt) {
    asm volatile("bar.arrive %0, %1;" :: "r"(id), "r"(cnt));
}
__device__ __forceinline__ void bar_wait(int id, int cnt) {
    asm volatile("bar.sync %0, %1;" :: "r"(id), "r"(cnt));
}

// ---------------- kernel 0: transpose x -> xTh (fp16) + xT_lo (residual) ----------------
__global__ void transpose_kernel(const float* __restrict__ x) {
    __shared__ float tile[32][33];
    int bf = blockIdx.z;
    int bb = bf >> 5, f = bf & 31;
    int n0 = blockIdx.x * 32, m0 = blockIdx.y * 32;
    int tx = threadIdx.x, ty = threadIdx.y;
    const float* src = x + (size_t)bf * (C_ * M_);
#pragma unroll
    for (int r = 0; r < 32; r += 8)
        tile[ty + r][tx] = src[(size_t)(n0 + ty + r) * M_ + m0 + tx];
    __syncthreads();
#pragma unroll
    for (int r = 0; r < 32; r += 8) {
        int m = m0 + ty + r, n = n0 + tx;
        float v = tile[tx][ty + r];
        __half h = __float2half_rn(v);
        __half lo = __float2half_rn(v - __half2float(h));
        size_t idx = ((size_t)(bb * M_ + m) * F_ + f) * C_ + n;
        g_xTh[idx] = h;
        g_xT_lo[idx] = lo;
    }
}

// ---------------- kernel 1: warp-specialized HMMA hop GEMMs ----------------
// smem (halves): As [256][LDA] @0 (persistent), Xs [32][LDA] @67584, StgH @76032
// warps 8-15: producers (stream A chunk c, STS fp16, bar.arrive(1+c))
// warps 0-7 : consumers (bar.sync(1+c), MMA hop0; then all warps hop1)
#define HOP_SMEM 168960
__global__ __launch_bounds__(512, 1)
void hop_kernel(const float* __restrict__ b0,
                const float* __restrict__ b1,
                const float* __restrict__ b2) {
    extern __shared__ __align__(16) uint16_t sm[];
    uint16_t* As   = sm;
    uint16_t* Xs   = sm + 67584;
    uint16_t* StgH = sm + 76032;

    int bx = blockIdx.x;
    int base = bx % 3;
    int pair = bx / 3;
    const float* A = (base == 0 ? b0 : base == 1 ? b1 : b2) + (size_t)pair * (C_ * C_);
    const float4* A4 = (const float4*)A;

    int t = threadIdx.x;
    int w = t >> 5;
    int l = t & 31;
    int g = l >> 2;
    int tig = l & 3;
    int lrow = l & 15;
    int lhalf = (l >> 4) & 1;

    uint32_t xs_b = smem_u32(Xs);
    uint32_t as_b = smem_u32(As);

    // hop0 consumer mapping: 8 warps -> 2 f-tiles x 4 v-slices(64)
    int cm = (w >> 2) * 16;
    int cv = (w & 3) * 64;
    uint32_t cx_off = (uint32_t)((cm + lrow) * LDA + lhalf * 8) * 2;
    uint32_t cb_off = (uint32_t)(lrow * LDA + cv + lhalf * 8) * 2;
    // hop1 mapping: 16 warps -> 2 f-tiles x 8 v-slices(32)
    int hm = (w >> 3) * 16;
    int hv = (w & 7) * 32;
    uint32_t hx_off = (uint32_t)((hm + lrow) * LDA + lhalf * 8) * 2;
    uint32_t hb_off = (uint32_t)(lrow * LDA + hv + lhalf * 8) * 2;

    // ---- Xs load (all threads) ----
    {
        const uint4* xsrc = (const uint4*)(g_xTh + (size_t)pair * (F_ * C_));
#pragma unroll
        for (int r = 0; r < 2; ++r) {
            int i = t + 512 * r;
            int f = i >> 5, q = i & 31;
            *(uint4*)&Xs[f * LDA + q * 8] = xsrc[i];
        }
    }
    __syncthreads();

    if (w >= 8) {
        // ================= producer: stream A, fill persistent As =================
        int pt = t - 256;                         // 0..255
        float4 va[8];
#pragma unroll
        for (int r = 0; r < 8; ++r) va[r] = A4[pt + 256 * r];
#pragma unroll 1
        for (int c = 0; c < 8; ++c) {
            float4 vb[8];
            if (c + 1 < 8) {
#pragma unroll
                for (int r = 0; r < 8; ++r) vb[r] = A4[(c + 1) * 2048 + pt + 256 * r];
            }
#pragma unroll
            for (int r = 0; r < 8; ++r) {
                int i = pt + 256 * r;
                int nloc = i >> 6, q = i & 63;
                uint32_t p0 = pack_h2(va[r].x, va[r].y);
                uint32_t p1 = pack_h2(va[r].z, va[r].w);
                *(uint2*)&As[(c * 32 + nloc) * LDA + q * 4] = make_uint2(p0, p1);
            }
            bar_arrive(1 + c, 512);
#pragma unroll
            for (int r = 0; r < 8; ++r) va[r] = vb[r];
        }
    } else {
        // ================= consumer: hop0 MMA =================
        float acc[8][4];
#pragma unroll
        for (int j = 0; j < 8; ++j)
#pragma unroll
            for (int q = 0; q < 4; ++q) acc[j][q] = 0.f;

        for (int c = 0; c < 8; ++c) {
            bar_wait(1 + c, 512);
#pragma unroll
            for (int ks = 0; ks < 2; ++ks) {
                int k = c * 32 + ks * 16;
                uint32_t xh[4];
                ldm_x4(xh, xs_b + cx_off + (uint32_t)k * 2);
                uint32_t rofs = cb_off + (uint32_t)(k * LDA) * 2;
#pragma unroll
                for (int jj = 0; jj < 4; ++jj) {
                    uint32_t b4[4];
                    ldm_x4t(b4, as_b + rofs + jj * 32);
                    mma_f16(acc[2 * jj],     xh, b4);
                    mma_f16(acc[2 * jj + 1], xh, b4 + 2);
                }
            }
        }
        bar_wait(9, 256);     // consumers done reading Xs(x)
        // U -> Xs (for hop1) and StgH (for scratch)
#pragma unroll
        for (int j = 0; j < 8; ++j) {
            int col = cv + 8 * j + 2 * tig;
            int r0 = cm + g, r1 = cm + g + 8;
            uint32_t p0 = pack_h2(acc[j][0], acc[j][1]);
            uint32_t p1 = pack_h2(acc[j][2], acc[j][3]);
            *(uint32_t*)&Xs[r0 * LDA + col] = p0;
            *(uint32_t*)&StgH[r0 * LDA + col] = p0;
            *(uint32_t*)&Xs[r1 * LDA + col] = p1;
            *(uint32_t*)&StgH[r1 * LDA + col] = p1;
        }
    }
    __syncthreads();

    // ---- copy U -> scratch (all threads) ----
    {
        __half* scr = g_scratch_h + ((size_t)(base * 2 + 0) * PAIRS + pair) * (F_ * C_);
#pragma unroll
        for (int r = 0; r < 2; ++r) {
            int i = t + 512 * r;
            int f = i >> 5, q = i & 31;
            ((uint4*)scr)[i] = *(const uint4*)&StgH[f * LDA + q * 8];
        }
    }

    // ================= hop1: all 16 warps, all-smem =================
    float a2[4][4];
#pragma unroll
    for (int j = 0; j < 4; ++j)
#pragma unroll
        for (int q = 0; q < 4; ++q) a2[j][q] = 0.f;

#pragma unroll 4
    for (int ks = 0; ks < 16; ++ks) {
        int k = ks * 16;
        uint32_t xh[4];
        ldm_x4(xh, xs_b + hx_off + (uint32_t)k * 2);
        uint32_t rofs = hb_off + (uint32_t)(k * LDA) * 2;
#pragma unroll
        for (int jj = 0; jj < 2; ++jj) {
            uint32_t b4[4];
            ldm_x4t(b4, as_b + rofs + jj * 32);
            mma_f16(a2[2 * jj],     xh, b4);
            mma_f16(a2[2 * jj + 1], xh, b4 + 2);
        }
    }
    __syncthreads();    // U scratch-copy done by all; StgH reusable

#pragma unroll
    for (int j = 0; j < 4; ++j) {
        int col = hv + 8 * j + 2 * tig;
        int r0 = hm + g, r1 = hm + g + 8;
        *(uint32_t*)&StgH[r0 * LDA + col] = pack_h2(a2[j][0], a2[j][1]);
        *(uint32_t*)&StgH[r1 * LDA + col] = pack_h2(a2[j][2], a2[j][3]);
    }
    __syncthreads();
    {
        __half* scr = g_scratch_h + ((size_t)(base * 2 + 1) * PAIRS + pair) * (F_ * C_);
#pragma unroll
        for (int r = 0; r < 2; ++r) {
            int i = t + 512 * r;
            int f = i >> 5, q = i & 31;
            ((uint4*)scr)[i] = *(const uint4*)&StgH[f * LDA + q * 8];
        }
    }
}

// ---------------- kernel 2: channel mix on HMMA (R11 champion) ----------------
#define LDW 264
#define MIX_SMEM ((16896 * 2 + 4 * 16 * 264) * 2)
__global__ __launch_bounds__(256, 2)
void mix_kernel(const float* __restrict__ W,
                const float* __restrict__ bias,
                float* __restrict__ y) {
    extern __shared__ __align__(16) uint16_t ms[];
    uint16_t* Whi = ms;
    uint16_t* Wlo = ms + 16896;
    uint16_t* Ht  = ms + 33792;   // 4 tiles of 16*264

    int pair = blockIdx.x;
    int bb = pair >> 6, m = pair & 63;
    int t = threadIdx.x;
    int w = t >> 5;
    int l = t & 31;
    int g = l >> 2;
    int tig = l & 3;
    int ot = (w >> 1) * 16;
    int vh = (w & 1) * 128;

    uint32_t whi_b = smem_u32(Whi);
    uint32_t wlo_b = smem_u32(Wlo);
    uint32_t ht_b  = smem_u32(Ht);

    int lrow = l & 15;
    int lhalf = (l >> 4) & 1;
    uint32_t w_off = (uint32_t)((ot + lrow) * LDW + lhalf * 8) * 2;
    uint32_t h_off = (uint32_t)(lrow * LDW + vh + lhalf * 8) * 2;

    {
        const float2* W2 = (const float2*)W;
        for (int i = t; i < 7168; i += 256) {
            int o = i / 112, kk = i % 112;
            float2 wv = W2[i];
            uint32_t hi, lo;
            split2h(wv.x, wv.y, hi, lo);
            ((uint32_t*)Whi)[o * (LDW / 2) + kk] = hi;
            ((uint32_t*)Wlo)[o * (LDW / 2) + kk] = lo;
        }
    }
    {
        const uint4* s0 = (const uint4*)(g_xTh + (size_t)pair * (F_ * C_));
        const uint4* sl = (const uint4*)(g_xT_lo + (size_t)pair * (F_ * C_));
#pragma unroll
        for (int r = 0; r < 2; ++r) {
            int i = t + 256 * r;
            int f = i >> 5, q = i & 31;
            *(uint4*)&Ht[0 * 4224 + f * LDW + q * 8] = s0[i];
            *(uint4*)&Ht[2 * 4224 + f * LDW + q * 8] = sl[i];
            *(uint4*)&Ht[3 * 4224 + f * LDW + q * 8] = sl[i + 512];
        }
    }
    __syncthreads();

    float acc[16][4];
#pragma unroll
    for (int j = 0; j < 16; ++j)
#pragma unroll
        for (int q = 0; q < 4; ++q) acc[j][q] = 0.f;

    uint4 ldgbuf[2];
    for (int ft = 0; ft < 14; ++ft) {
        int cur = ft & 1;
        if (ft + 1 < 14) {
            int nf = ft + 1;
            const uint4* src;
            if (nf < 2) {
                src = (const uint4*)(g_xTh + (size_t)pair * (F_ * C_) + nf * 16 * C_);
            } else {
                int blk = (nf - 2) >> 1;
                int fr  = ((nf - 2) & 1) * 16;
                src = (const uint4*)(g_scratch_h + ((size_t)blk * PAIRS + pair) * (F_ * C_) + fr * C_);
            }
            ldgbuf[0] = src[t];
            ldgbuf[1] = src[t + 256];
        }
        uint32_t whi4[4], wlo4[4];
        ldm_x4(whi4, whi_b + w_off + (uint32_t)ft * 32);
        ldm_x4(wlo4, wlo_b + w_off + (uint32_t)ft * 32);
        uint32_t hb = ht_b + (uint32_t)cur * 4224 * 2;
#pragma unroll
        for (int jj = 0; jj < 8; ++jj) {
            uint32_t b4[4];
            ldm_x4t(b4, hb + h_off + jj * 32);
            mma_f16(acc[2 * jj],     whi4, b4);
            mma_f16(acc[2 * jj],     wlo4, b4);
            mma_f16(acc[2 * jj + 1], whi4, b4 + 2);
            mma_f16(acc[2 * jj + 1], wlo4, b4 + 2);
        }
        if (ft < 2) {
            uint32_t hlb = ht_b + (uint32_t)(2 + ft) * 4224 * 2;
#pragma unroll
            for (int jj = 0; jj < 8; ++jj) {
                uint32_t b4[4];
                ldm_x4t(b4, hlb + h_off + jj * 32);
                mma_f16(acc[2 * jj],     whi4, b4);
                mma_f16(acc[2 * jj + 1], whi4, b4 + 2);
            }
        }
        __syncthreads();
        if (ft + 1 < 14) {
            int nxt = cur ^ 1;
#pragma unroll
            for (int r = 0; r < 2; ++r) {
                int i = t + 256 * r;
                int f = i >> 5, q = i & 31;
                *(uint4*)&Ht[nxt * 4224 + f * LDW + q * 8] = ldgbuf[r];
            }
        }
        __syncthreads();
    }

#pragma unroll
    for (int j = 0; j < 16; ++j) {
        int col = vh + (j >> 1) * 16 + (j & 1) * 8 + 2 * tig;
        int r0 = ot + g, r1 = ot + g + 8;
        float bv0 = __ldg(&bias[r0]);
        float bv1 = __ldg(&bias[r1]);
        size_t base0 = ((size_t)(bb * CO_ + r0) * C_ + col) * M_ + m;
        size_t base1 = ((size_t)(bb * CO_ + r1) * C_ + col) * M_ + m;
        y[base0]      = acc[j][0] + bv0;
        y[base0 + M_] = acc[j][1] + bv0;
        y[base1]      = acc[j][2] + bv1;
        y[base1 + M_] = acc[j][3] + bv1;
    }
}

extern "C" void kernel_launch(void* const* d_in, const int* in_sizes, int n_in,
                              void* d_out, int out_size) {
    const float* x    = (const float*)d_in[0];
    const float* b0   = (const float*)d_in[1];
    const float* b1   = (const float*)d_in[2];
    const float* b2   = (const float*)d_in[3];
    const float* W    = (const float*)d_in[4];
    const float* bias = (const float*)d_in[5];
    float* y = (float*)d_out;

    cudaFuncSetAttribute(hop_kernel, cudaFuncAttributeMaxDynamicSharedMemorySize, HOP_SMEM);
    cudaFuncSetAttribute(mix_kernel, cudaFuncAttributeMaxDynamicSharedMemorySize, MIX_SMEM);

    transpose_kernel<<<dim3(C_ / 32, M_ / 32, B_ * F_), dim3(32, 8)>>>(x);
    hop_kernel<<<PAIRS * 3, 512, HOP_SMEM>>>(b0, b1, b2);
    mix_kernel<<<PAIRS, 256, MIX_SMEM>>>(W, bias, y);
}

// round 16
// speedup vs baseline: 1.0242x; 1.0242x over previous
#include <cuda_runtime.h>
#include <cuda_bf16.h>
#include <cuda_fp16.h>
#include <cstdint>

// x: [8,32,256,64] f32 | baseK: [8,64,256,256] f32 | W: [64,224] | b: [64] | y: [8,64,256,64]
#define B_   8
#define F_   32
#define C_   256
#define M_   64
#define CO_  64
#define PAIRS 512
#define LDA  264             // padded row stride (halves): 528B

__device__ __half g_scratch_h[6 * PAIRS * F_ * C_];   // hop results, fp16
__device__ __half g_xTh[PAIRS * F_ * C_];             // fp16(x) transposed
__device__ __half g_xT_lo[PAIRS * F_ * C_];           // fp16 residual of x

// ---------------- helpers ----------------
__device__ __forceinline__ uint32_t smem_u32(const void* p) {
    uint32_t a;
    asm("{ .reg .u64 t; cvta.to.shared.u64 t, %1; cvt.u32.u64 %0, t; }" : "=r"(a) : "l"(p));
    return a;
}
__device__ __forceinline__ uint32_t pack_h2(float x, float y) {
    uint32_t r;
    asm("cvt.rn.f16x2.f32 %0, %1, %2;" : "=r"(r) : "f"(y), "f"(x));
    return r;
}
__device__ __forceinline__ void split2h(float x, float y, uint32_t& hi, uint32_t& lo) {
    hi = pack_h2(x, y);
    float hx, hy;
    asm("{ .reg .f16 a,b; mov.b32 {a,b}, %2; cvt.f32.f16 %0, a; cvt.f32.f16 %1, b; }"
        : "=f"(hx), "=f"(hy) : "r"(hi));
    lo = pack_h2(x - hx, y - hy);
}
__device__ __forceinline__ void ldm_x4(uint32_t* r, uint32_t addr) {
    asm volatile("ldmatrix.sync.aligned.m8n8.x4.shared.b16 {%0,%1,%2,%3}, [%4];"
                 : "=r"(r[0]), "=r"(r[1]), "=r"(r[2]), "=r"(r[3]) : "r"(addr));
}
__device__ __forceinline__ void ldm_x4t(uint32_t* r, uint32_t addr) {
    asm volatile("ldmatrix.sync.aligned.m8n8.x4.trans.shared.b16 {%0,%1,%2,%3}, [%4];"
                 : "=r"(r[0]), "=r"(r[1]), "=r"(r[2]), "=r"(r[3]) : "r"(addr));
}
__device__ __forceinline__ void mma_f16(float* d, const uint32_t* a, const uint32_t* b) {
    asm volatile("mma.sync.aligned.m16n8k16.row.col.f32.f16.f16.f32 "
                 "{%0,%1,%2,%3}, {%4,%5,%6,%7}, {%8,%9}, {%0,%1,%2,%3};"
                 : "+f"(d[0]), "+f"(d[1]), "+f"(d[2]), "+f"(d[3])
                 : "r"(a[0]), "r"(a[1]), "r"(a[2]), "r"(a[3]), "r"(b[0]), "r"(b[1]));
}
__device__ __forceinline__ void cp_async16(uint32_t saddr, const void* gptr) {
    asm volatile("cp.async.cg.shared.global [%0], [%1], 16;" :: "r"(saddr), "l"(gptr));
}
__device__ __forceinline__ void cp_commit() {
    asm volatile("cp.async.commit_group;" ::: "memory");
}
template <int N>
__device__ __forceinline__ void cp_wait() {
    asm volatile("cp.async.wait_group %0;" :: "n"(N) : "memory");
}

// ---------------- kernel 0: transpose x -> xTh (fp16) + xT_lo (residual) ----------------
__global__ void transpose_kernel(const float* __restrict__ x) {
    __shared__ float tile[32][33];
    int bf = blockIdx.z;
    int bb = bf >> 5, f = bf & 31;
    int n0 = blockIdx.x * 32, m0 = blockIdx.y * 32;
    int tx = threadIdx.x, ty = threadIdx.y;
    const float* src = x + (size_t)bf * (C_ * M_);
#pragma unroll
    for (int r = 0; r < 32; r += 8)
        tile[ty + r][tx] = src[(size_t)(n0 + ty + r) * M_ + m0 + tx];
    __syncthreads();
#pragma unroll
    for (int r = 0; r < 32; r += 8) {
        int m = m0 + ty + r, n = n0 + tx;
        float v = tile[tx][ty + r];
        __half h = __float2half_rn(v);
        __half lo = __float2half_rn(v - __half2float(h));
        size_t idx = ((size_t)(bb * M_ + m) * F_ + f) * C_ + n;
        g_xTh[idx] = h;
        g_xT_lo[idx] = lo;
    }
}

// ---------------- kernel 1: HMMA hop GEMMs, cp.async-staged persistent A ----------------
// smem (halves):
//   As   [256][LDA] @ 0       (67584 h = 135168 B) persistent fp16 A
//   Xs   [32][LDA]  @ 67584   (8448 h)
//   Stg0 f32 32KB   @ 76032   (16384 h)   cp.async staging ring
//   Stg1 f32 32KB   @ 92416   (16384 h)
//   StgH aliases Stg0
// total 108800 h = 217600 B
#define SM_XS   67584
#define SM_STG0 76032
#define SM_STG1 92416
#define HOP_SMEM 217600
__global__ __launch_bounds__(512, 1)
void hop_kernel(const float* __restrict__ b0,
                const float* __restrict__ b1,
                const float* __restrict__ b2) {
    extern __shared__ __align__(16) uint16_t sm[];
    uint16_t* As   = sm;
    uint16_t* Xs   = sm + SM_XS;
    uint16_t* StgH = sm + SM_STG0;

    int bx = blockIdx.x;
    int base = bx % 3;
    int pair = bx / 3;
    const float* A = (base == 0 ? b0 : base == 1 ? b1 : b2) + (size_t)pair * (C_ * C_);
    const char* Ag = (const char*)A;

    int t = threadIdx.x;
    int w = t >> 5;
    int l = t & 31;
    int g = l >> 2;
    int tig = l & 3;
    int lrow = l & 15;
    int lhalf = (l >> 4) & 1;

    uint32_t xs_b = smem_u32(Xs);
    uint32_t as_b = smem_u32(As);
    uint32_t stg_b[2] = { smem_u32(sm + SM_STG0), smem_u32(sm + SM_STG1) };
    float* stgf[2] = { (float*)(sm + SM_STG0), (float*)(sm + SM_STG1) };

    // hop mapping: 16 warps -> 2 f-tiles x 8 v-slices(32)
    int hm = (w >> 3) * 16;
    int hv = (w & 7) * 32;
    uint32_t hx_off = (uint32_t)((hm + lrow) * LDA + lhalf * 8) * 2;
    uint32_t hb_off = (uint32_t)(lrow * LDA + hv + lhalf * 8) * 2;

    // ---- issue A chunks 0,1 via cp.async (32 rows = 32KB each; 4x16B per thread) ----
#pragma unroll
    for (int r = 0; r < 4; ++r)
        cp_async16(stg_b[0] + (t + 512 * r) * 16, Ag + (size_t)(t + 512 * r) * 16);
    cp_commit();
#pragma unroll
    for (int r = 0; r < 4; ++r)
        cp_async16(stg_b[1] + (t + 512 * r) * 16, Ag + 32768 + (size_t)(t + 512 * r) * 16);
    cp_commit();

    // ---- Xs load ----
    {
        const uint4* xsrc = (const uint4*)(g_xTh + (size_t)pair * (F_ * C_));
#pragma unroll
        for (int r = 0; r < 2; ++r) {
            int i = t + 512 * r;
            int f = i >> 5, q = i & 31;
            *(uint4*)&Xs[f * LDA + q * 8] = xsrc[i];
        }
    }
    __syncthreads();

    // ================= hop 0: convert + MMA pipeline =================
    float acc[4][4];
#pragma unroll
    for (int j = 0; j < 4; ++j)
#pragma unroll
        for (int q = 0; q < 4; ++q) acc[j][q] = 0.f;

#pragma unroll 1
    for (int c = 0; c < 8; ++c) {
        int buf = c & 1;
        if (c < 7) cp_wait<1>(); else cp_wait<0>();
        // convert own granules: thread t wrote f32 idx [4(t+512r), 4(t+512r)+4)
#pragma unroll
        for (int r = 0; r < 4; ++r) {
            int gr = t + 512 * r;
            float4 v = *(const float4*)&stgf[buf][gr * 4];
            int row = gr >> 6;             // 64 granules (256 f32) per row
            int col = (gr & 63) * 4;
            uint32_t p0 = pack_h2(v.x, v.y);
            uint32_t p1 = pack_h2(v.z, v.w);
            *(uint2*)&As[(c * 32 + row) * LDA + col] = make_uint2(p0, p1);
        }
        __syncthreads();                   // As(c) visible; staging buf free
        if (c + 2 < 8) {
#pragma unroll
            for (int r = 0; r < 4; ++r)
                cp_async16(stg_b[buf] + (t + 512 * r) * 16,
                           Ag + (size_t)(c + 2) * 32768 + (size_t)(t + 512 * r) * 16);
            cp_commit();
        }
#pragma unroll
        for (int ks = 0; ks < 2; ++ks) {
            int k = c * 32 + ks * 16;
            uint32_t xh[4];
            ldm_x4(xh, xs_b + hx_off + (uint32_t)k * 2);
            uint32_t rofs = hb_off + (uint32_t)(k * LDA) * 2;
#pragma unroll
            for (int jj = 0; jj < 2; ++jj) {
                uint32_t b4[4];
                ldm_x4t(b4, as_b + rofs + jj * 32);
                mma_f16(acc[2 * jj],     xh, b4);
                mma_f16(acc[2 * jj + 1], xh, b4 + 2);
            }
        }
    }
    __syncthreads();                       // all MMA reads of As/Xs done

    // epilogue hop 0: StgH fp16 + X update
#pragma unroll
    for (int j = 0; j < 4; ++j) {
        int col = hv + 8 * j + 2 * tig;
        int r0 = hm + g, r1 = hm + g + 8;
        uint32_t p0 = pack_h2(acc[j][0], acc[j][1]);
        uint32_t p1 = pack_h2(acc[j][2], acc[j][3]);
        *(uint32_t*)&StgH[r0 * LDA + col] = p0;
        *(uint32_t*)&StgH[r1 * LDA + col] = p1;
        *(uint32_t*)&Xs[r0 * LDA + col] = p0;
        *(uint32_t*)&Xs[r1 * LDA + col] = p1;
    }
    __syncthreads();
    {
        __half* scr = g_scratch_h + ((size_t)(base * 2 + 0) * PAIRS + pair) * (F_ * C_);
#pragma unroll
        for (int r = 0; r < 2; ++r) {
            int i = t + 512 * r;
            int f = i >> 5, q = i & 31;
            ((uint4*)scr)[i] = *(const uint4*)&StgH[f * LDA + q * 8];
        }
    }
    __syncthreads();

    // ================= hop 1: all from smem =================
#pragma unroll
    for (int j = 0; j < 4; ++j)
#pragma unroll
        for (int q = 0; q < 4; ++q) acc[j][q] = 0.f;

#pragma unroll 4
    for (int ks = 0; ks < 16; ++ks) {
        int k = ks * 16;
        uint32_t xh[4];
        ldm_x4(xh, xs_b + hx_off + (uint32_t)k * 2);
        uint32_t rofs = hb_off + (uint32_t)(k * LDA) * 2;
#pragma unroll
        for (int jj = 0; jj < 2; ++jj) {
            uint32_t b4[4];
            ldm_x4t(b4, as_b + rofs + jj * 32);
            mma_f16(acc[2 * jj],     xh, b4);
            mma_f16(acc[2 * jj + 1], xh, b4 + 2);
        }
    }
    __syncthreads();
#pragma unroll
    for (int j = 0; j < 4; ++j) {
        int col = hv + 8 * j + 2 * tig;
        int r0 = hm + g, r1 = hm + g + 8;
        *(uint32_t*)&StgH[r0 * LDA + col] = pack_h2(acc[j][0], acc[j][1]);
        *(uint32_t*)&StgH[r1 * LDA + col] = pack_h2(acc[j][2], acc[j][3]);
    }
    __syncthreads();
    {
        __half* scr = g_scratch_h + ((size_t)(base * 2 + 1) * PAIRS + pair) * (F_ * C_);
#pragma unroll
        for (int r = 0; r < 2; ++r) {
            int i = t + 512 * r;
            int f = i >> 5, q = i & 31;
            ((uint4*)scr)[i] = *(const uint4*)&StgH[f * LDA + q * 8];
        }
    }
}

// ---------------- kernel 2: channel mix on HMMA (R11 champion) ----------------
#define LDW 264
#define MIX_SMEM ((16896 * 2 + 4 * 16 * 264) * 2)
__global__ __launch_bounds__(256, 2)
void mix_kernel(const float* __restrict__ W,
                const float* __restrict__ bias,
                float* __restrict__ y) {
    extern __shared__ __align__(16) uint16_t ms[];
    uint16_t* Whi = ms;
    uint16_t* Wlo = ms + 16896;
    uint16_t* Ht  = ms + 33792;   // 4 tiles of 16*264

    int pair = blockIdx.x;
    int bb = pair >> 6, m = pair & 63;
    int t = threadIdx.x;
    int w = t >> 5;
    int l = t & 31;
    int g = l >> 2;
    int tig = l & 3;
    int ot = (w >> 1) * 16;
    int vh = (w & 1) * 128;

    uint32_t whi_b = smem_u32(Whi);
    uint32_t wlo_b = smem_u32(Wlo);
    uint32_t ht_b  = smem_u32(Ht);

    int lrow = l & 15;
    int lhalf = (l >> 4) & 1;
    uint32_t w_off = (uint32_t)((ot + lrow) * LDW + lhalf * 8) * 2;
    uint32_t h_off = (uint32_t)(lrow * LDW + vh + lhalf * 8) * 2;

    {
        const float2* W2 = (const float2*)W;
        for (int i = t; i < 7168; i += 256) {
            int o = i / 112, kk = i % 112;
            float2 wv = W2[i];
            uint32_t hi, lo;
            split2h(wv.x, wv.y, hi, lo);
            ((uint32_t*)Whi)[o * (LDW / 2) + kk] = hi;
            ((uint32_t*)Wlo)[o * (LDW / 2) + kk] = lo;
        }
    }
    {
        const uint4* s0 = (const uint4*)(g_xTh + (size_t)pair * (F_ * C_));
        const uint4* sl = (const uint4*)(g_xT_lo + (size_t)pair * (F_ * C_));
#pragma unroll
        for (int r = 0; r < 2; ++r) {
            int i = t + 256 * r;
            int f = i >> 5, q = i & 31;
            *(uint4*)&Ht[0 * 4224 + f * LDW + q * 8] = s0[i];
            *(uint4*)&Ht[2 * 4224 + f * LDW + q * 8] = sl[i];
            *(uint4*)&Ht[3 * 4224 + f * LDW + q * 8] = sl[i + 512];
        }
    }
    __syncthreads();

    float acc[16][4];
#pragma unroll
    for (int j = 0; j < 16; ++j)
#pragma unroll
        for (int q = 0; q < 4; ++q) acc[j][q] = 0.f;

    uint4 ldgbuf[2];
    for (int ft = 0; ft < 14; ++ft) {
        int cur = ft & 1;
        if (ft + 1 < 14) {
            int nf = ft + 1;
            const uint4* src;
            if (nf < 2) {
                src = (const uint4*)(g_xTh + (size_t)pair * (F_ * C_) + nf * 16 * C_);
            } else {
                int blk = (nf - 2) >> 1;
                int fr  = ((nf - 2) & 1) * 16;
                src = (const uint4*)(g_scratch_h + ((size_t)blk * PAIRS + pair) * (F_ * C_) + fr * C_);
            }
            ldgbuf[0] = src[t];
            ldgbuf[1] = src[t + 256];
        }
        uint32_t whi4[4], wlo4[4];
        ldm_x4(whi4, whi_b + w_off + (uint32_t)ft * 32);
        ldm_x4(wlo4, wlo_b + w_off + (uint32_t)ft * 32);
        uint32_t hb = ht_b + (uint32_t)cur * 4224 * 2;
#pragma unroll
        for (int jj = 0; jj < 8; ++jj) {
            uint32_t b4[4];
            ldm_x4t(b4, hb + h_off + jj * 32);
            mma_f16(acc[2 * jj],     whi4, b4);
            mma_f16(acc[2 * jj],     wlo4, b4);
            mma_f16(acc[2 * jj + 1], whi4, b4 + 2);
            mma_f16(acc[2 * jj + 1], wlo4, b4 + 2);
        }
        if (ft < 2) {
            uint32_t hlb = ht_b + (uint32_t)(2 + ft) * 4224 * 2;
#pragma unroll
            for (int jj = 0; jj < 8; ++jj) {
                uint32_t b4[4];
                ldm_x4t(b4, hlb + h_off + jj * 32);
                mma_f16(acc[2 * jj],     whi4, b4);
                mma_f16(acc[2 * jj + 1], whi4, b4 + 2);
            }
        }
        __syncthreads();
        if (ft + 1 < 14) {
            int nxt = cur ^ 1;
#pragma unroll
            for (int r = 0; r < 2; ++r) {
                int i = t + 256 * r;
                int f = i >> 5, q = i & 31;
                *(uint4*)&Ht[nxt * 4224 + f * LDW + q * 8] = ldgbuf[r];
            }
        }
        __syncthreads();
    }

#pragma unroll
    for (int j = 0; j < 16; ++j) {
        int col = vh + (j >> 1) * 16 + (j & 1) * 8 + 2 * tig;
        int r0 = ot + g, r1 = ot + g + 8;
        float bv0 = __ldg(&bias[r0]);
        float bv1 = __ldg(&bias[r1]);
        size_t base0 = ((size_t)(bb * CO_ + r0) * C_ + col) * M_ + m;
        size_t base1 = ((size_t)(bb * CO_ + r1) * C_ + col) * M_ + m;
        y[base0]      = acc[j][0] + bv0;
        y[base0 + M_] = acc[j][1] + bv0;
        y[base1]      = acc[j][2] + bv1;
        y[base1 + M_] = acc[j][3] + bv1;
    }
}

extern "C" void kernel_launch(void* const* d_in, const int* in_sizes, int n_in,
                              void* d_out, int out_size) {
    const float* x    = (const float*)d_in[0];
    const float* b0   = (const float*)d_in[1];
    const float* b1   = (const float*)d_in[2];
    const float* b2   = (const float*)d_in[3];
    const float* W    = (const float*)d_in[4];
    const float* bias = (const float*)d_in[5];
    float* y = (float*)d_out;

    cudaFuncSetAttribute(hop_kernel, cudaFuncAttributeMaxDynamicSharedMemorySize, HOP_SMEM);
    cudaFuncSetAttribute(mix_kernel, cudaFuncAttributeMaxDynamicSharedMemorySize, MIX_SMEM);

    transpose_kernel<<<dim3(C_ / 32, M_ / 32, B_ * F_), dim3(32, 8)>>>(x);
    hop_kernel<<<PAIRS * 3, 512, HOP_SMEM>>>(b0, b1, b2);
    mix_kernel<<<PAIRS, 256, MIX_SMEM>>>(W, bias, y);
}